// round 9
// baseline (speedup 1.0000x reference)
#include <cuda_runtime.h>
#include <math.h>

// ---------------- problem constants ----------------
#define N_CAM   2
#define PH      96
#define PW      144
#define NPTS    200
#define MIN_D   1.0f
#define MAX_D   4000.0f
#define VD      32
#define VH      128
#define VW      384
#define VOXELSZ 2.5f

#define DHW   (VD*VH*VW)
#define HW    (VH*VW)
#define PHW   (PH*PW)                             // pixels per camera = 13824
#define NRAYS (N_CAM*PH*PW)
#define STEP_D ((MAX_D - MIN_D) / (float)(NPTS - 1))

#define HX (VOXELSZ * (VW - 1) * 0.5f)
#define HY (VOXELSZ * (VH - 1) * 0.5f)
#define HZ (VOXELSZ * (VD - 1) * 0.5f)

#define THREADS    256
// 8 lanes per PIXEL (merged: 1 ray x LPR8; split: 2 rays x LPR4)
#define RAY_BLOCKS ((PHW * 8) / THREADS)          // 432 (exact)
#define NCOL4      (HW / 4)                       // 12288
#define BEV_BLOCKS ((NCOL4 * 2) / THREADS)        // 96 (exact, 2 threads/column)
#define NBLOCKS    (RAY_BLOCKS + BEV_BLOCKS)      // 528

// global accumulators (reset by the last block each replay)
__device__ float    g_accum[3] = {0.0f, 0.0f, 0.0f};
__device__ unsigned g_count = 0;

__device__ __forceinline__ float huber01(float x, float y) {
    float d = x - y;
    float v = fmaf(d * d, 100.0f, 1.0f);
    return (sqrtf(v) - 1.0f) * 0.1f;
}

// Fully specialized per-pixel ray work. LPRC/MERGED are compile-time so the
// compose shuffles unroll, shifts are immediate, and (for MERGED) the camera
// parameter loads are warp-uniform.
template<int LPRC, bool MERGED>
__device__ __forceinline__ void ray_work(
    int idx, int sub,
    const float* __restrict__ dens, const float* __restrict__ cols,
    const float* __restrict__ tsil, const float* __restrict__ timg,
    const float* __restrict__ focal, const float* __restrict__ princ,
    const float* __restrict__ Rm,   const float* __restrict__ Tv,
    float& csum, float& ssum)
{
    constexpr int LPRSH = (LPRC == 8) ? 3 : 2;
    const int cam = MERGED ? 0 : (sub >> 2);     // constexpr-0 when merged
    const int sl  = MERGED ? sub : (sub & 3);

    int w = idx % PW;
    int h = idx / PW;

    float fx = focal[cam*2+0], fy = focal[cam*2+1];
    float px = princ[cam*2+0], py = princ[cam*2+1];
    float dcx = ((float)w + 0.5f - px) / fx;
    float dcy = ((float)h + 0.5f - py) / fy;

    const float* R = Rm + cam*9;
    float Tx = Tv[cam*3+0], Ty = Tv[cam*3+1], Tz = Tv[cam*3+2];

    float dx = dcx*R[0] + dcy*R[1] + R[2];
    float dy = dcx*R[3] + dcy*R[4] + R[5];
    float dz = dcx*R[6] + dcy*R[7] + R[8];
    float ox = -(Tx*R[0] + Ty*R[1] + Tz*R[2]);
    float oy = -(Tx*R[3] + Ty*R[4] + Tz*R[5]);
    float oz = -(Tx*R[6] + Ty*R[7] + Tz*R[8]);

    // grid-space linear form: g_axis(t) = A + B*t (slab test AND samples)
    const float cx = 0.5f * (VW - 1), cy = 0.5f * (VH - 1), cz = 0.5f * (VD - 1);
    float Ax = ox / HX * cx + cx, Bx = dx / HX * cx;
    float Ay = oy / HY * cy + cy, By = dy / HY * cy;
    float Az = oz / HZ * cz + cz, Bz = dz / HZ * cz;

    float tmin = MIN_D, tmax = MAX_D;
    {
        const float lo = -1.001f, hi = (float)VW + 0.001f;
        if (fabsf(Bx) > 1e-20f) {
            float rB = __fdividef(1.0f, Bx);
            float t1 = (lo - Ax) * rB, t2 = (hi - Ax) * rB;
            tmin = fmaxf(tmin, fminf(t1, t2)); tmax = fminf(tmax, fmaxf(t1, t2));
        } else if (Ax <= lo || Ax >= hi) { tmax = tmin - 1.0f; }
    }
    {
        const float lo = -1.001f, hi = (float)VH + 0.001f;
        if (fabsf(By) > 1e-20f) {
            float rB = __fdividef(1.0f, By);
            float t1 = (lo - Ay) * rB, t2 = (hi - Ay) * rB;
            tmin = fmaxf(tmin, fminf(t1, t2)); tmax = fminf(tmax, fmaxf(t1, t2));
        } else if (Ay <= lo || Ay >= hi) { tmax = tmin - 1.0f; }
    }
    {
        const float lo = -1.001f, hi = (float)VD + 0.001f;
        if (fabsf(Bz) > 1e-20f) {
            float rB = __fdividef(1.0f, Bz);
            float t1 = (lo - Az) * rB, t2 = (hi - Az) * rB;
            tmin = fmaxf(tmin, fminf(t1, t2)); tmax = fminf(tmax, fmaxf(t1, t2));
        } else if (Az <= lo || Az >= hi) { tmax = tmin - 1.0f; }
    }

    int i0 = 0, i1 = -1;
    if (tmax >= tmin) {
        i0 = (int)ceilf ((tmin - MIN_D) / STEP_D - 1e-4f);
        i1 = (int)floorf((tmax - MIN_D) / STEP_D + 1e-4f);
        if (i0 < 0) i0 = 0;
        if (i1 > NPTS - 1) i1 = NPTS - 1;
    }

    // this lane's contiguous chunk of samples
    int nsamp = i1 - i0 + 1;                     // may be <= 0
    int chunk = (nsamp + LPRC - 1) >> LPRSH;     // per-lane count (>=0)
    int s0 = i0 + sl * chunk;
    int s1 = s0 + chunk - 1;
    if (s1 > i1) s1 = i1;

    float trans = 1.0f;                          // local prod(1-d)
    float fr = 0.0f, fg = 0.0f, fb = 0.0f;       // local over-composited rgb

    for (int i = s0; i <= s1; ++i) {
        float t  = fmaf((float)i, STEP_D, MIN_D);
        float gx = fmaf(t, Bx, Ax);
        float gy = fmaf(t, By, Ay);
        float gz = fmaf(t, Bz, Az);

        float x0f = floorf(gx), y0f = floorf(gy), z0f = floorf(gz);
        float frx = gx - x0f, fry = gy - y0f, frz = gz - z0f;
        int ix0 = (int)x0f, iy0 = (int)y0f, iz0 = (int)z0f;

        // validity folded into per-axis weights; indices clamped (branch-free)
        float wx0 = (ix0     >= 0 && ix0     < VW) ? 1.0f - frx : 0.0f;
        float wx1 = (ix0 + 1 >= 0 && ix0 + 1 < VW) ? frx        : 0.0f;
        float wy0 = (iy0     >= 0 && iy0     < VH) ? 1.0f - fry : 0.0f;
        float wy1 = (iy0 + 1 >= 0 && iy0 + 1 < VH) ? fry        : 0.0f;
        float wz0 = (iz0     >= 0 && iz0     < VD) ? 1.0f - frz : 0.0f;
        float wz1 = (iz0 + 1 >= 0 && iz0 + 1 < VD) ? frz        : 0.0f;

        int x0 = min(max(ix0,     0), VW - 1);
        int x1 = min(max(ix0 + 1, 0), VW - 1);
        int y0 = min(max(iy0,     0), VH - 1) * VW;
        int y1 = min(max(iy0 + 1, 0), VH - 1) * VW;
        int z0 = min(max(iz0,     0), VD - 1) * HW;
        int z1 = min(max(iz0 + 1, 0), VD - 1) * HW;

        int f000 = z0 + y0 + x0, f001 = z0 + y0 + x1;
        int f010 = z0 + y1 + x0, f011 = z0 + y1 + x1;
        int f100 = z1 + y0 + x0, f101 = z1 + y0 + x1;
        int f110 = z1 + y1 + x0, f111 = z1 + y1 + x1;

        float w000 = wz0*wy0*wx0, w001 = wz0*wy0*wx1;
        float w010 = wz0*wy1*wx0, w011 = wz0*wy1*wx1;
        float w100 = wz1*wy0*wx0, w101 = wz1*wy0*wx1;
        float w110 = wz1*wy1*wx0, w111 = wz1*wy1*wx1;

        // issue all loads up front (max MLP)
        float d000 = __ldg(dens + f000), d001 = __ldg(dens + f001);
        float d010 = __ldg(dens + f010), d011 = __ldg(dens + f011);
        float d100 = __ldg(dens + f100), d101 = __ldg(dens + f101);
        float d110 = __ldg(dens + f110), d111 = __ldg(dens + f111);

        const float* cr = cols;
        const float* cg = cols + DHW;
        const float* cb = cols + 2*DHW;
        float r000 = __ldg(cr + f000), r001 = __ldg(cr + f001);
        float r010 = __ldg(cr + f010), r011 = __ldg(cr + f011);
        float r100 = __ldg(cr + f100), r101 = __ldg(cr + f101);
        float r110 = __ldg(cr + f110), r111 = __ldg(cr + f111);
        float g000 = __ldg(cg + f000), g001 = __ldg(cg + f001);
        float g010 = __ldg(cg + f010), g011 = __ldg(cg + f011);
        float g100 = __ldg(cg + f100), g101 = __ldg(cg + f101);
        float g110 = __ldg(cg + f110), g111 = __ldg(cg + f111);
        float b000 = __ldg(cb + f000), b001 = __ldg(cb + f001);
        float b010 = __ldg(cb + f010), b011 = __ldg(cb + f011);
        float b100 = __ldg(cb + f100), b101 = __ldg(cb + f101);
        float b110 = __ldg(cb + f110), b111 = __ldg(cb + f111);

        float ad = w000*d000 + w001*d001 + w010*d010 + w011*d011
                 + w100*d100 + w101*d101 + w110*d110 + w111*d111;
        float ar = w000*r000 + w001*r001 + w010*r010 + w011*r011
                 + w100*r100 + w101*r101 + w110*r110 + w111*r111;
        float ag = w000*g000 + w001*g001 + w010*g010 + w011*g011
                 + w100*g100 + w101*g101 + w110*g110 + w111*g111;
        float ab = w000*b000 + w001*b001 + w010*b010 + w011*b011
                 + w100*b100 + w101*b101 + w110*b110 + w111*b111;

        float wgt = ad * trans;
        fr = fmaf(wgt, ar, fr);
        fg = fmaf(wgt, ag, fg);
        fb = fmaf(wgt, ab, fb);
        trans *= (1.0f - ad);
    }

    // ---- compose lane-chunks: (F,T) ⊗ (F',T') = (F + T F', T T') ----
    #pragma unroll
    for (int o = 1; o < LPRC; o <<= 1) {
        float Tn  = __shfl_down_sync(0xffffffffu, trans, o, LPRC);
        float frn = __shfl_down_sync(0xffffffffu, fr,    o, LPRC);
        float fgn = __shfl_down_sync(0xffffffffu, fg,    o, LPRC);
        float fbn = __shfl_down_sync(0xffffffffu, fb,    o, LPRC);
        fr = fmaf(trans, frn, fr);
        fg = fmaf(trans, fgn, fg);
        fb = fmaf(trans, fbn, fb);
        trans *= Tn;
    }

    csum = 0.0f; ssum = 0.0f;
    if (sl == 0) {
        float opacity = 1.0f - trans;
        if (MERGED) {
            // one render serves both cameras' losses
            ssum = huber01(opacity, tsil[idx]) + huber01(opacity, tsil[idx + PHW]);
            const float* t0 = timg + (size_t)idx * 3;
            const float* t1 = timg + (size_t)(idx + PHW) * 3;
            csum = huber01(fr, t0[0]) + huber01(fg, t0[1]) + huber01(fb, t0[2])
                 + huber01(fr, t1[0]) + huber01(fg, t1[1]) + huber01(fb, t1[2]);
        } else {
            int ray = cam * PHW + idx;
            ssum = huber01(opacity, tsil[ray]);
            const float* ti = timg + (size_t)ray * 3;
            csum = huber01(fr, ti[0]) + huber01(fg, ti[1]) + huber01(fb, ti[2]);
        }
    }
}

__global__ void __launch_bounds__(THREADS)
fused_loss_kernel(
    const float* __restrict__ dens,   // (VD,VH,VW)
    const float* __restrict__ cols,   // (3,VD,VH,VW)
    const float* __restrict__ tsil,   // (N_CAM,PH,PW)
    const float* __restrict__ timg,   // (N_CAM,PH,PW,3)
    const float* __restrict__ focal,
    const float* __restrict__ princ,
    const float* __restrict__ Rm,
    const float* __restrict__ Tv,
    float* __restrict__ out)
{
    __shared__ float s_a[THREADS/32], s_b[THREADS/32];
    __shared__ bool  s_last;

    const int tid  = threadIdx.x;
    const int lane = tid & 31;
    const int warp = tid >> 5;

    if (blockIdx.x < RAY_BLOCKS) {
        // ---------------- ray blocks: 8 lanes per pixel ----------------
        int g   = blockIdx.x * THREADS + tid;     // < PHW*8 exactly
        int idx = g >> 3;                          // pixel id (0..PHW-1)
        int sub = g & 7;                           // lane-within-pixel

        // grid-uniform: are the two cameras identical?
        bool same = (focal[0] == focal[2]) && (focal[1] == focal[3])
                 && (princ[0] == princ[2]) && (princ[1] == princ[3]);
        #pragma unroll
        for (int k = 0; k < 9; ++k) same = same && (Rm[k] == Rm[9+k]);
        #pragma unroll
        for (int k = 0; k < 3; ++k) same = same && (Tv[k] == Tv[3+k]);

        float csum, ssum;
        if (same) {
            ray_work<8, true >(idx, sub, dens, cols, tsil, timg,
                               focal, princ, Rm, Tv, csum, ssum);
        } else {
            ray_work<4, false>(idx, sub, dens, cols, tsil, timg,
                               focal, princ, Rm, Tv, csum, ssum);
        }

        // block reduce, then one atomic per block
        #pragma unroll
        for (int o = 16; o > 0; o >>= 1) {
            csum += __shfl_down_sync(0xffffffffu, csum, o);
            ssum += __shfl_down_sync(0xffffffffu, ssum, o);
        }
        if (lane == 0) { s_a[warp] = csum; s_b[warp] = ssum; }
        __syncthreads();
        if (warp == 0) {
            float a = (lane < THREADS/32) ? s_a[lane] : 0.0f;
            float b = (lane < THREADS/32) ? s_b[lane] : 0.0f;
            #pragma unroll
            for (int o = 4; o > 0; o >>= 1) {
                a += __shfl_down_sync(0xffffffffu, a, o);
                b += __shfl_down_sync(0xffffffffu, b, o);
            }
            if (lane == 0) {
                atomicAdd(&g_accum[0], a);
                atomicAdd(&g_accum[1], b);
            }
        }
    } else {
        // -------- BEV blocks: mean |max_z dens|, 2 threads per column --------
        int gb    = (blockIdx.x - RAY_BLOCKS) * (THREADS / 32) + warp; // global warp id
        int cidx  = gb * 16 + (lane & 15);       // float4 column index (< NCOL4)
        int zbase = (lane >> 4) * 16;            // 0 or 16

        const float4* d4 = (const float4*)dens;
        float4 m = __ldg(d4 + cidx + zbase * NCOL4);
        #pragma unroll
        for (int z = 1; z < 16; ++z) {
            float4 v = __ldg(d4 + cidx + (zbase + z) * NCOL4);
            m.x = fmaxf(m.x, v.x); m.y = fmaxf(m.y, v.y);
            m.z = fmaxf(m.z, v.z); m.w = fmaxf(m.w, v.w);
        }
        m.x = fmaxf(m.x, __shfl_xor_sync(0xffffffffu, m.x, 16));
        m.y = fmaxf(m.y, __shfl_xor_sync(0xffffffffu, m.y, 16));
        m.z = fmaxf(m.z, __shfl_xor_sync(0xffffffffu, m.z, 16));
        m.w = fmaxf(m.w, __shfl_xor_sync(0xffffffffu, m.w, 16));

        float bsum = (lane < 16)
                   ? (fabsf(m.x) + fabsf(m.y) + fabsf(m.z) + fabsf(m.w))
                   : 0.0f;
        #pragma unroll
        for (int o = 8; o > 0; o >>= 1)
            bsum += __shfl_down_sync(0xffffffffu, bsum, o);
        if (lane == 0) s_a[warp] = bsum;
        __syncthreads();
        if (warp == 0) {
            float a = (lane < THREADS/32) ? s_a[lane] : 0.0f;
            #pragma unroll
            for (int o = 4; o > 0; o >>= 1)
                a += __shfl_down_sync(0xffffffffu, a, o);
            if (lane == 0)
                atomicAdd(&g_accum[2], a);
        }
    }

    // ---------------- last block finalizes ----------------
    if (tid == 0) {
        __threadfence();
        unsigned prev = atomicAdd(&g_count, 1u);
        s_last = (prev == NBLOCKS - 1);
    }
    __syncthreads();

    if (s_last && tid == 0) {
        float a = g_accum[0];
        float b = g_accum[1];
        float c = g_accum[2];
        out[0] = a * (1.0f / (float)(NRAYS * 3));
        out[1] = b * (1.0f / (float)NRAYS);
        out[2] = c * (1.0f / (float)HW);
        // reset for next graph replay
        g_accum[0] = 0.0f;
        g_accum[1] = 0.0f;
        g_accum[2] = 0.0f;
        g_count = 0;
    }
}

extern "C" void kernel_launch(void* const* d_in, const int* in_sizes, int n_in,
                              void* d_out, int out_size) {
    const float* dens  = (const float*)d_in[0];
    const float* cols  = (const float*)d_in[1];
    const float* tsil  = (const float*)d_in[2];
    const float* timg  = (const float*)d_in[3];
    const float* focal = (const float*)d_in[4];
    const float* princ = (const float*)d_in[5];
    const float* Rm    = (const float*)d_in[6];
    const float* Tv    = (const float*)d_in[7];
    float* out = (float*)d_out;

    fused_loss_kernel<<<NBLOCKS, THREADS>>>(dens, cols, tsil, timg,
                                            focal, princ, Rm, Tv, out);
}

// round 10
// speedup vs baseline: 1.1831x; 1.1831x over previous
#include <cuda_runtime.h>
#include <math.h>

// ---------------- problem constants ----------------
#define N_CAM   2
#define PH      96
#define PW      144
#define NPTS    200
#define MIN_D   1.0f
#define MAX_D   4000.0f
#define VD      32
#define VH      128
#define VW      384
#define VOXELSZ 2.5f

#define DHW   (VD*VH*VW)
#define HW    (VH*VW)
#define PHW   (PH*PW)                             // pixels per camera = 13824
#define NRAYS (N_CAM*PH*PW)
#define STEP_D ((MAX_D - MIN_D) / (float)(NPTS - 1))

#define HX (VOXELSZ * (VW - 1) * 0.5f)
#define HY (VOXELSZ * (VH - 1) * 0.5f)
#define HZ (VOXELSZ * (VD - 1) * 0.5f)

#define THREADS    256
// grid sized for the SPLIT path: 8 lanes per pixel (2 rays x 4 lanes)
#define RAY_BLOCKS ((PHW * 8) / THREADS)          // 432 (exact)
// merged path uses only the first half: 4 lanes per pixel, 1 ray per pixel
#define MERGED_RAY_BLOCKS ((PHW * 4) / THREADS)   // 216 (exact)
#define NCOL4      (HW / 4)                       // 12288
#define BEV_BLOCKS ((NCOL4 * 2) / THREADS)        // 96 (exact, 2 threads/column)
#define NBLOCKS    (RAY_BLOCKS + BEV_BLOCKS)      // 528

// global accumulators (reset by the last block each replay)
__device__ float    g_accum[3] = {0.0f, 0.0f, 0.0f};
__device__ unsigned g_count = 0;

__device__ __forceinline__ float huber01(float x, float y) {
    float d = x - y;
    float v = fmaf(d * d, 100.0f, 1.0f);
    return (sqrtf(v) - 1.0f) * 0.1f;
}

// LPR=4 ray work, compile-time MERGED flag. Warp shape: 8 pixels x 4 lanes
// (identical to the best split kernel). MERGED => cam is constexpr 0 and the
// single render feeds both cameras' losses.
template<bool MERGED>
__device__ __forceinline__ void ray_work4(
    int idx, int cam, int sl,
    const float* __restrict__ dens, const float* __restrict__ cols,
    const float* __restrict__ tsil, const float* __restrict__ timg,
    const float* __restrict__ focal, const float* __restrict__ princ,
    const float* __restrict__ Rm,   const float* __restrict__ Tv,
    float& csum, float& ssum)
{
    if (MERGED) cam = 0;

    int w = idx % PW;
    int h = idx / PW;

    float fx = focal[cam*2+0], fy = focal[cam*2+1];
    float px = princ[cam*2+0], py = princ[cam*2+1];
    float dcx = ((float)w + 0.5f - px) / fx;
    float dcy = ((float)h + 0.5f - py) / fy;

    const float* R = Rm + cam*9;
    float Tx = Tv[cam*3+0], Ty = Tv[cam*3+1], Tz = Tv[cam*3+2];

    float dx = dcx*R[0] + dcy*R[1] + R[2];
    float dy = dcx*R[3] + dcy*R[4] + R[5];
    float dz = dcx*R[6] + dcy*R[7] + R[8];
    float ox = -(Tx*R[0] + Ty*R[1] + Tz*R[2]);
    float oy = -(Tx*R[3] + Ty*R[4] + Tz*R[5]);
    float oz = -(Tx*R[6] + Ty*R[7] + Tz*R[8]);

    // grid-space linear form: g_axis(t) = A + B*t (slab test AND samples)
    const float cx = 0.5f * (VW - 1), cy = 0.5f * (VH - 1), cz = 0.5f * (VD - 1);
    float Ax = ox / HX * cx + cx, Bx = dx / HX * cx;
    float Ay = oy / HY * cy + cy, By = dy / HY * cy;
    float Az = oz / HZ * cz + cz, Bz = dz / HZ * cz;

    float tmin = MIN_D, tmax = MAX_D;
    {
        const float lo = -1.001f, hi = (float)VW + 0.001f;
        if (fabsf(Bx) > 1e-20f) {
            float rB = __fdividef(1.0f, Bx);
            float t1 = (lo - Ax) * rB, t2 = (hi - Ax) * rB;
            tmin = fmaxf(tmin, fminf(t1, t2)); tmax = fminf(tmax, fmaxf(t1, t2));
        } else if (Ax <= lo || Ax >= hi) { tmax = tmin - 1.0f; }
    }
    {
        const float lo = -1.001f, hi = (float)VH + 0.001f;
        if (fabsf(By) > 1e-20f) {
            float rB = __fdividef(1.0f, By);
            float t1 = (lo - Ay) * rB, t2 = (hi - Ay) * rB;
            tmin = fmaxf(tmin, fminf(t1, t2)); tmax = fminf(tmax, fmaxf(t1, t2));
        } else if (Ay <= lo || Ay >= hi) { tmax = tmin - 1.0f; }
    }
    {
        const float lo = -1.001f, hi = (float)VD + 0.001f;
        if (fabsf(Bz) > 1e-20f) {
            float rB = __fdividef(1.0f, Bz);
            float t1 = (lo - Az) * rB, t2 = (hi - Az) * rB;
            tmin = fmaxf(tmin, fminf(t1, t2)); tmax = fminf(tmax, fmaxf(t1, t2));
        } else if (Az <= lo || Az >= hi) { tmax = tmin - 1.0f; }
    }

    int i0 = 0, i1 = -1;
    if (tmax >= tmin) {
        i0 = (int)ceilf ((tmin - MIN_D) / STEP_D - 1e-4f);
        i1 = (int)floorf((tmax - MIN_D) / STEP_D + 1e-4f);
        if (i0 < 0) i0 = 0;
        if (i1 > NPTS - 1) i1 = NPTS - 1;
    }

    // this lane's contiguous chunk of samples
    int nsamp = i1 - i0 + 1;                     // may be <= 0
    int chunk = (nsamp + 3) >> 2;                // per-lane count (>=0)
    int s0 = i0 + sl * chunk;
    int s1 = s0 + chunk - 1;
    if (s1 > i1) s1 = i1;

    float trans = 1.0f;                          // local prod(1-d)
    float fr = 0.0f, fg = 0.0f, fb = 0.0f;       // local over-composited rgb

    for (int i = s0; i <= s1; ++i) {
        float t  = fmaf((float)i, STEP_D, MIN_D);
        float gx = fmaf(t, Bx, Ax);
        float gy = fmaf(t, By, Ay);
        float gz = fmaf(t, Bz, Az);

        float x0f = floorf(gx), y0f = floorf(gy), z0f = floorf(gz);
        float frx = gx - x0f, fry = gy - y0f, frz = gz - z0f;
        int ix0 = (int)x0f, iy0 = (int)y0f, iz0 = (int)z0f;

        // validity folded into per-axis weights; indices clamped (branch-free)
        float wx0 = (ix0     >= 0 && ix0     < VW) ? 1.0f - frx : 0.0f;
        float wx1 = (ix0 + 1 >= 0 && ix0 + 1 < VW) ? frx        : 0.0f;
        float wy0 = (iy0     >= 0 && iy0     < VH) ? 1.0f - fry : 0.0f;
        float wy1 = (iy0 + 1 >= 0 && iy0 + 1 < VH) ? fry        : 0.0f;
        float wz0 = (iz0     >= 0 && iz0     < VD) ? 1.0f - frz : 0.0f;
        float wz1 = (iz0 + 1 >= 0 && iz0 + 1 < VD) ? frz        : 0.0f;

        int x0 = min(max(ix0,     0), VW - 1);
        int x1 = min(max(ix0 + 1, 0), VW - 1);
        int y0 = min(max(iy0,     0), VH - 1) * VW;
        int y1 = min(max(iy0 + 1, 0), VH - 1) * VW;
        int z0 = min(max(iz0,     0), VD - 1) * HW;
        int z1 = min(max(iz0 + 1, 0), VD - 1) * HW;

        int f000 = z0 + y0 + x0, f001 = z0 + y0 + x1;
        int f010 = z0 + y1 + x0, f011 = z0 + y1 + x1;
        int f100 = z1 + y0 + x0, f101 = z1 + y0 + x1;
        int f110 = z1 + y1 + x0, f111 = z1 + y1 + x1;

        float w000 = wz0*wy0*wx0, w001 = wz0*wy0*wx1;
        float w010 = wz0*wy1*wx0, w011 = wz0*wy1*wx1;
        float w100 = wz1*wy0*wx0, w101 = wz1*wy0*wx1;
        float w110 = wz1*wy1*wx0, w111 = wz1*wy1*wx1;

        // issue all loads up front (max MLP)
        float d000 = __ldg(dens + f000), d001 = __ldg(dens + f001);
        float d010 = __ldg(dens + f010), d011 = __ldg(dens + f011);
        float d100 = __ldg(dens + f100), d101 = __ldg(dens + f101);
        float d110 = __ldg(dens + f110), d111 = __ldg(dens + f111);

        const float* cr = cols;
        const float* cg = cols + DHW;
        const float* cb = cols + 2*DHW;
        float r000 = __ldg(cr + f000), r001 = __ldg(cr + f001);
        float r010 = __ldg(cr + f010), r011 = __ldg(cr + f011);
        float r100 = __ldg(cr + f100), r101 = __ldg(cr + f101);
        float r110 = __ldg(cr + f110), r111 = __ldg(cr + f111);
        float g000 = __ldg(cg + f000), g001 = __ldg(cg + f001);
        float g010 = __ldg(cg + f010), g011 = __ldg(cg + f011);
        float g100 = __ldg(cg + f100), g101 = __ldg(cg + f101);
        float g110 = __ldg(cg + f110), g111 = __ldg(cg + f111);
        float b000 = __ldg(cb + f000), b001 = __ldg(cb + f001);
        float b010 = __ldg(cb + f010), b011 = __ldg(cb + f011);
        float b100 = __ldg(cb + f100), b101 = __ldg(cb + f101);
        float b110 = __ldg(cb + f110), b111 = __ldg(cb + f111);

        float ad = w000*d000 + w001*d001 + w010*d010 + w011*d011
                 + w100*d100 + w101*d101 + w110*d110 + w111*d111;
        float ar = w000*r000 + w001*r001 + w010*r010 + w011*r011
                 + w100*r100 + w101*r101 + w110*r110 + w111*r111;
        float ag = w000*g000 + w001*g001 + w010*g010 + w011*g011
                 + w100*g100 + w101*g101 + w110*g110 + w111*g111;
        float ab = w000*b000 + w001*b001 + w010*b010 + w011*b011
                 + w100*b100 + w101*b101 + w110*b110 + w111*b111;

        float wgt = ad * trans;
        fr = fmaf(wgt, ar, fr);
        fg = fmaf(wgt, ag, fg);
        fb = fmaf(wgt, ab, fb);
        trans *= (1.0f - ad);
    }

    // ---- compose the 4 lane-chunks: (F,T) ⊗ (F',T') = (F + T F', T T') ----
    #pragma unroll
    for (int o = 1; o < 4; o <<= 1) {
        float Tn  = __shfl_down_sync(0xffffffffu, trans, o, 4);
        float frn = __shfl_down_sync(0xffffffffu, fr,    o, 4);
        float fgn = __shfl_down_sync(0xffffffffu, fg,    o, 4);
        float fbn = __shfl_down_sync(0xffffffffu, fb,    o, 4);
        fr = fmaf(trans, frn, fr);
        fg = fmaf(trans, fgn, fg);
        fb = fmaf(trans, fbn, fb);
        trans *= Tn;
    }

    if (sl == 0) {
        float opacity = 1.0f - trans;
        if (MERGED) {
            // one render serves both cameras' losses
            ssum = huber01(opacity, tsil[idx]) + huber01(opacity, tsil[idx + PHW]);
            const float* t0 = timg + (size_t)idx * 3;
            const float* t1 = timg + (size_t)(idx + PHW) * 3;
            csum = huber01(fr, t0[0]) + huber01(fg, t0[1]) + huber01(fb, t0[2])
                 + huber01(fr, t1[0]) + huber01(fg, t1[1]) + huber01(fb, t1[2]);
        } else {
            int ray = cam * PHW + idx;
            ssum = huber01(opacity, tsil[ray]);
            const float* ti = timg + (size_t)ray * 3;
            csum = huber01(fr, ti[0]) + huber01(fg, ti[1]) + huber01(fb, ti[2]);
        }
    }
}

__global__ void __launch_bounds__(THREADS)
fused_loss_kernel(
    const float* __restrict__ dens,   // (VD,VH,VW)
    const float* __restrict__ cols,   // (3,VD,VH,VW)
    const float* __restrict__ tsil,   // (N_CAM,PH,PW)
    const float* __restrict__ timg,   // (N_CAM,PH,PW,3)
    const float* __restrict__ focal,
    const float* __restrict__ princ,
    const float* __restrict__ Rm,
    const float* __restrict__ Tv,
    float* __restrict__ out)
{
    __shared__ float s_a[THREADS/32], s_b[THREADS/32];
    __shared__ bool  s_last;

    const int tid  = threadIdx.x;
    const int lane = tid & 31;
    const int warp = tid >> 5;

    if (blockIdx.x < RAY_BLOCKS) {
        // grid-uniform: are the two cameras identical?
        bool same = (focal[0] == focal[2]) && (focal[1] == focal[3])
                 && (princ[0] == princ[2]) && (princ[1] == princ[3]);
        #pragma unroll
        for (int k = 0; k < 9; ++k) same = same && (Rm[k] == Rm[9+k]);
        #pragma unroll
        for (int k = 0; k < 3; ++k) same = same && (Tv[k] == Tv[3+k]);

        float csum = 0.0f, ssum = 0.0f;
        if (same) {
            // merged: 4 lanes per pixel; only the first 216 blocks have work
            if (blockIdx.x < MERGED_RAY_BLOCKS) {
                int g   = blockIdx.x * THREADS + tid;   // < PHW*4 exactly
                int idx = g >> 2;
                int sl  = g & 3;
                ray_work4<true>(idx, 0, sl, dens, cols, tsil, timg,
                                focal, princ, Rm, Tv, csum, ssum);
            }
        } else {
            // split: 8 lanes per pixel = 2 rays x 4 lanes (proven path)
            int g   = blockIdx.x * THREADS + tid;       // < PHW*8 exactly
            int idx = g >> 3;
            int sub = g & 7;
            ray_work4<false>(idx, sub >> 2, sub & 3, dens, cols, tsil, timg,
                             focal, princ, Rm, Tv, csum, ssum);
        }

        // block reduce, then one atomic per block
        #pragma unroll
        for (int o = 16; o > 0; o >>= 1) {
            csum += __shfl_down_sync(0xffffffffu, csum, o);
            ssum += __shfl_down_sync(0xffffffffu, ssum, o);
        }
        if (lane == 0) { s_a[warp] = csum; s_b[warp] = ssum; }
        __syncthreads();
        if (warp == 0) {
            float a = (lane < THREADS/32) ? s_a[lane] : 0.0f;
            float b = (lane < THREADS/32) ? s_b[lane] : 0.0f;
            #pragma unroll
            for (int o = 4; o > 0; o >>= 1) {
                a += __shfl_down_sync(0xffffffffu, a, o);
                b += __shfl_down_sync(0xffffffffu, b, o);
            }
            if (lane == 0) {
                atomicAdd(&g_accum[0], a);
                atomicAdd(&g_accum[1], b);
            }
        }
    } else {
        // -------- BEV blocks: mean |max_z dens|, 2 threads per column --------
        int gb    = (blockIdx.x - RAY_BLOCKS) * (THREADS / 32) + warp; // global warp id
        int cidx  = gb * 16 + (lane & 15);       // float4 column index (< NCOL4)
        int zbase = (lane >> 4) * 16;            // 0 or 16

        const float4* d4 = (const float4*)dens;
        float4 m = __ldg(d4 + cidx + zbase * NCOL4);
        #pragma unroll
        for (int z = 1; z < 16; ++z) {
            float4 v = __ldg(d4 + cidx + (zbase + z) * NCOL4);
            m.x = fmaxf(m.x, v.x); m.y = fmaxf(m.y, v.y);
            m.z = fmaxf(m.z, v.z); m.w = fmaxf(m.w, v.w);
        }
        m.x = fmaxf(m.x, __shfl_xor_sync(0xffffffffu, m.x, 16));
        m.y = fmaxf(m.y, __shfl_xor_sync(0xffffffffu, m.y, 16));
        m.z = fmaxf(m.z, __shfl_xor_sync(0xffffffffu, m.z, 16));
        m.w = fmaxf(m.w, __shfl_xor_sync(0xffffffffu, m.w, 16));

        float bsum = (lane < 16)
                   ? (fabsf(m.x) + fabsf(m.y) + fabsf(m.z) + fabsf(m.w))
                   : 0.0f;
        #pragma unroll
        for (int o = 8; o > 0; o >>= 1)
            bsum += __shfl_down_sync(0xffffffffu, bsum, o);
        if (lane == 0) s_a[warp] = bsum;
        __syncthreads();
        if (warp == 0) {
            float a = (lane < THREADS/32) ? s_a[lane] : 0.0f;
            #pragma unroll
            for (int o = 4; o > 0; o >>= 1)
                a += __shfl_down_sync(0xffffffffu, a, o);
            if (lane == 0)
                atomicAdd(&g_accum[2], a);
        }
    }

    // ---------------- last block finalizes ----------------
    if (tid == 0) {
        __threadfence();
        unsigned prev = atomicAdd(&g_count, 1u);
        s_last = (prev == NBLOCKS - 1);
    }
    __syncthreads();

    if (s_last && tid == 0) {
        float a = g_accum[0];
        float b = g_accum[1];
        float c = g_accum[2];
        out[0] = a * (1.0f / (float)(NRAYS * 3));
        out[1] = b * (1.0f / (float)NRAYS);
        out[2] = c * (1.0f / (float)HW);
        // reset for next graph replay
        g_accum[0] = 0.0f;
        g_accum[1] = 0.0f;
        g_accum[2] = 0.0f;
        g_count = 0;
    }
}

extern "C" void kernel_launch(void* const* d_in, const int* in_sizes, int n_in,
                              void* d_out, int out_size) {
    const float* dens  = (const float*)d_in[0];
    const float* cols  = (const float*)d_in[1];
    const float* tsil  = (const float*)d_in[2];
    const float* timg  = (const float*)d_in[3];
    const float* focal = (const float*)d_in[4];
    const float* princ = (const float*)d_in[5];
    const float* Rm    = (const float*)d_in[6];
    const float* Tv    = (const float*)d_in[7];
    float* out = (float*)d_out;

    fused_loss_kernel<<<NBLOCKS, THREADS>>>(dens, cols, tsil, timg,
                                            focal, princ, Rm, Tv, out);
}